// round 5
// baseline (speedup 1.0000x reference)
#include <cuda_runtime.h>
#include <cuda_fp16.h>
#include <cstdint>

#define SS   2048
#define DQ   4096
#define DKV  1024
#define SCL  (0.08838834764831845f * 1.4426950408889634f)

// smem layout (bytes)
#define OFF_STAGE 0        // 64KB: Q fp16 (prologue), then K/V fp32 staging
#define OFF_K16   65536    // 16KB: K tile fp16, 64 rows x 256B, swizzled
#define OFF_V16   81920    // 16KB: V tile fp16
#define OFF_P     98304    // 32KB: P tile fp16, 256 rows x 128B, swizzled
#define SMEM_BYTES 131072

__device__ __forceinline__ uint32_t smem_u32(const void* p) {
    uint32_t a;
    asm("{ .reg .u64 t; cvta.to.shared.u64 t, %1; cvt.u32.u64 %0, t; }" : "=r"(a) : "l"(p));
    return a;
}
__device__ __forceinline__ float fast_ex2(float x) {
    float y; asm("ex2.approx.ftz.f32 %0, %1;" : "=f"(y) : "f"(x)); return y;
}
__device__ __forceinline__ void ldsm_x4(uint32_t* r, uint32_t addr) {
    asm volatile("ldmatrix.sync.aligned.m8n8.x4.shared.b16 {%0,%1,%2,%3}, [%4];"
        : "=r"(r[0]), "=r"(r[1]), "=r"(r[2]), "=r"(r[3]) : "r"(addr));
}
__device__ __forceinline__ void ldsm_x4_t(uint32_t* r, uint32_t addr) {
    asm volatile("ldmatrix.sync.aligned.m8n8.x4.trans.shared.b16 {%0,%1,%2,%3}, [%4];"
        : "=r"(r[0]), "=r"(r[1]), "=r"(r[2]), "=r"(r[3]) : "r"(addr));
}
__device__ __forceinline__ void mma16816(float* d, const uint32_t* a, const uint32_t* b) {
    asm volatile("mma.sync.aligned.m16n8k16.row.col.f32.f16.f16.f32 "
        "{%0,%1,%2,%3},{%4,%5,%6,%7},{%8,%9},{%0,%1,%2,%3};"
        : "+f"(d[0]), "+f"(d[1]), "+f"(d[2]), "+f"(d[3])
        : "r"(a[0]), "r"(a[1]), "r"(a[2]), "r"(a[3]), "r"(b[0]), "r"(b[1]));
}
__device__ __forceinline__ uint32_t packh2(float a, float b) {
    __half2 h = __floats2half2_rn(a, b);
    return *(uint32_t*)&h;
}
__device__ __forceinline__ void cp16(uint32_t dst, const void* src) {
    asm volatile("cp.async.cg.shared.global [%0], [%1], 16;" :: "r"(dst), "l"(src));
}

// CTA: 4 heads x 64 tokens = 256 q-rows; 8 warps x 32 rows; BN=64 keys/tile.
__global__ void __launch_bounds__(256, 1)
attn_hmma2(const float* __restrict__ q, const float* __restrict__ k,
           const float* __restrict__ v, float* __restrict__ out)
{
    extern __shared__ char sm[];
    const uint32_t sb = smem_u32(sm);
    const uint32_t sSt = sb + OFF_STAGE, sK = sb + OFF_K16,
                   sV = sb + OFF_V16,   sP = sb + OFF_P;

    const int tid  = threadIdx.x;
    const int warp = tid >> 5, lane = tid & 31;
    const int qb = 31 - (int)blockIdx.x;      // longest CTAs first
    const int kv = blockIdx.y, b = blockIdx.z;
    const int q0 = qb * 64;
    const int hbase = kv * 4;
    const int ntiles = qb + 1;
    const int wrow = (warp >> 1) * 64 + (warp & 1) * 32;   // warp's first row

    // ---- stage Q fp16 (pre-scaled) into staging buffer ----
    #pragma unroll
    for (int it = 0; it < 16; ++it) {
        int id  = tid + 256 * it;
        int row = id >> 4, ch = id & 15;
        int token = q0 + (row & 63);
        int head  = hbase + (row >> 6);
        const float4* gp = (const float4*)(q + (size_t)(b * SS + token) * DQ
                                             + head * 128 + ch * 8);
        float4 f0 = gp[0], f1 = gp[1];
        uint32_t h0 = packh2(f0.x * SCL, f0.y * SCL);
        uint32_t h1 = packh2(f0.z * SCL, f0.w * SCL);
        uint32_t h2 = packh2(f1.x * SCL, f1.y * SCL);
        uint32_t h3 = packh2(f1.z * SCL, f1.w * SCL);
        uint32_t addr = sSt + row * 256 + ((ch ^ (row & 7)) << 4);
        asm volatile("st.shared.v4.b32 [%0],{%1,%2,%3,%4};"
            :: "r"(addr), "r"(h0), "r"(h1), "r"(h2), "r"(h3));
    }
    __syncthreads();

    // ---- persistent Q fragments: qf[kstep][m-half][4]  (64 regs) ----
    uint32_t qf[8][2][4];
    #pragma unroll
    for (int mh = 0; mh < 2; ++mh) {
        int row = wrow + mh * 16 + (lane & 7) + ((lane >> 3) & 1) * 8;
        #pragma unroll
        for (int ks = 0; ks < 8; ++ks) {
            int chunk = ks * 2 + (lane >> 4);
            ldsm_x4(qf[ks][mh], sSt + row * 256 + ((chunk ^ (row & 7)) << 4));
        }
    }
    __syncthreads();   // staging free for K/V

    // ---- cp.async K/V tile -> fp32 staging (even/odd-chunk split layout) ----
    auto cpkv = [&](int jt) {
        const float* kb_ = k + (size_t)(b * SS + jt * 64) * DKV + kv * 128;
        const float* vb_ = v + (size_t)(b * SS + jt * 64) * DKV + kv * 128;
        #pragma unroll
        for (int i = 0; i < 8; ++i) {
            int g = tid + 256 * i;
            int row = g >> 5, c = g & 31;
            uint32_t dst = sSt + ((g & 1) << 14) + ((g >> 1) << 4);
            cp16(dst,         kb_ + (size_t)row * DKV + c * 4);
            cp16(dst + 32768, vb_ + (size_t)row * DKV + c * 4);
        }
        asm volatile("cp.async.commit_group;");
    };
    // ---- convert staging fp32 -> fp16 K/V tiles (swizzled) ----
    auto cvt = [&]() {
        #pragma unroll
        for (int i = 0; i < 4; ++i) {
            int f = tid + 256 * i;
            int row = f >> 4, h = f & 15;
            uint32_t so = (uint32_t)(row * 16 + h) << 4;
            uint32_t dsw = row * 256 + ((h ^ (row & 7)) << 4);
            float4 a  = *(const float4*)(sm + OFF_STAGE + so);
            float4 b2 = *(const float4*)(sm + OFF_STAGE + 16384 + so);
            asm volatile("st.shared.v4.b32 [%0],{%1,%2,%3,%4};"
                :: "r"(sK + dsw), "r"(packh2(a.x, a.y)), "r"(packh2(a.z, a.w)),
                   "r"(packh2(b2.x, b2.y)), "r"(packh2(b2.z, b2.w)));
            float4 c  = *(const float4*)(sm + OFF_STAGE + 32768 + so);
            float4 d2 = *(const float4*)(sm + OFF_STAGE + 49152 + so);
            asm volatile("st.shared.v4.b32 [%0],{%1,%2,%3,%4};"
                :: "r"(sV + dsw), "r"(packh2(c.x, c.y)), "r"(packh2(c.z, c.w)),
                   "r"(packh2(d2.x, d2.y)), "r"(packh2(d2.z, d2.w)));
        }
    };

    cpkv(0);
    asm volatile("cp.async.wait_group 0;");
    __syncthreads();
    cvt();
    __syncthreads();

    float o[2][16][4];
    #pragma unroll
    for (int mh = 0; mh < 2; ++mh)
        #pragma unroll
        for (int i = 0; i < 16; ++i)
            #pragma unroll
            for (int j = 0; j < 4; ++j) o[mh][i][j] = 0.0f;
    float lsum[2][2] = {{0.0f, 0.0f}, {0.0f, 0.0f}};

    for (int jt = 0; jt < ntiles; ++jt) {
        if (jt + 1 < ntiles) cpkv(jt + 1);   // overlaps with QK+PV

        // ---- QK^T + softmax + P store, 8 keys at a time ----
        const int Krow = (lane & 7);
        const int m    = lane >> 3;
        #pragma unroll
        for (int n2 = 0; n2 < 8; ++n2) {
            float s[2][4] = {{0,0,0,0},{0,0,0,0}};
            int kr = n2 * 8 + Krow;
            #pragma unroll
            for (int ks2 = 0; ks2 < 4; ++ks2) {
                uint32_t kb[4];
                int chunk = ks2 * 4 + m;
                ldsm_x4(kb, sK + kr * 256 + ((chunk ^ (kr & 7)) << 4));
                mma16816(s[0], qf[2*ks2][0],   kb);
                mma16816(s[0], qf[2*ks2+1][0], kb + 2);
                mma16816(s[1], qf[2*ks2][1],   kb);
                mma16816(s[1], qf[2*ks2+1][1], kb + 2);
            }
            #pragma unroll
            for (int mh = 0; mh < 2; ++mh) {
                int row0 = wrow + mh * 16 + (lane >> 2);
                int tok0 = q0 + (row0 & 63);
                int kg = jt * 64 + n2 * 8 + (lane & 3) * 2;
                float p00 = (kg     <= tok0)     ? fast_ex2(s[mh][0]) : 0.0f;
                float p01 = (kg + 1 <= tok0)     ? fast_ex2(s[mh][1]) : 0.0f;
                float p10 = (kg     <= tok0 + 8) ? fast_ex2(s[mh][2]) : 0.0f;
                float p11 = (kg + 1 <= tok0 + 8) ? fast_ex2(s[mh][3]) : 0.0f;
                lsum[mh][0] += p00 + p01;
                lsum[mh][1] += p10 + p11;
                int r1 = row0 + 8;
                uint32_t a0 = sP + row0 * 128 + ((n2 ^ (row0 & 7)) << 4) + (lane & 3) * 4;
                uint32_t a1 = sP + r1   * 128 + ((n2 ^ (r1   & 7)) << 4) + (lane & 3) * 4;
                asm volatile("st.shared.b32 [%0], %1;" :: "r"(a0), "r"(packh2(p00, p01)));
                asm volatile("st.shared.b32 [%0], %1;" :: "r"(a1), "r"(packh2(p10, p11)));
            }
        }
        __syncwarp();

        // ---- PV: O += P * V ----
        #pragma unroll
        for (int ks2 = 0; ks2 < 4; ++ks2) {
            uint32_t pf[2][4];
            #pragma unroll
            for (int mh = 0; mh < 2; ++mh) {
                int row = wrow + mh * 16 + (lane & 7) + ((lane >> 3) & 1) * 8;
                int chunk = ks2 * 2 + (lane >> 4);
                ldsm_x4(pf[mh], sP + row * 128 + ((chunk ^ (row & 7)) << 4));
            }
            int Vrow = ks2 * 16 + (m & 1) * 8 + (lane & 7);
            #pragma unroll
            for (int n2o = 0; n2o < 16; n2o += 2) {
                uint32_t vb[4];
                int chunk = n2o + (m >> 1);
                ldsm_x4_t(vb, sV + Vrow * 256 + ((chunk ^ (Vrow & 7)) << 4));
                mma16816(o[0][n2o],     pf[0], vb);
                mma16816(o[0][n2o + 1], pf[0], vb + 2);
                mma16816(o[1][n2o],     pf[1], vb);
                mma16816(o[1][n2o + 1], pf[1], vb + 2);
            }
        }

        if (jt + 1 < ntiles) {
            asm volatile("cp.async.wait_group 0;");
            __syncthreads();       // all warps done with K16/V16 + staging ready
            cvt();
            __syncthreads();       // new fp16 tiles visible
        }
    }

    // ---- epilogue ----
    #pragma unroll
    for (int mh = 0; mh < 2; ++mh) {
        float l0 = lsum[mh][0], l1 = lsum[mh][1];
        l0 += __shfl_xor_sync(0xffffffffu, l0, 1);
        l0 += __shfl_xor_sync(0xffffffffu, l0, 2);
        l1 += __shfl_xor_sync(0xffffffffu, l1, 1);
        l1 += __shfl_xor_sync(0xffffffffu, l1, 2);
        float inv0 = 1.0f / l0, inv1 = 1.0f / l1;

        int row0 = wrow + mh * 16 + (lane >> 2);
        int tok0 = q0 + (row0 & 63);
        int head = hbase + (warp >> 1);
        float* r0p = out + (size_t)(b * SS + tok0) * DQ + head * 128 + (lane & 3) * 2;
        float* r1p = r0p + (size_t)8 * DQ;
        #pragma unroll
        for (int n2o = 0; n2o < 16; ++n2o) {
            *(float2*)(r0p + n2o * 8) =
                make_float2(o[mh][n2o][0] * inv0, o[mh][n2o][1] * inv0);
            *(float2*)(r1p + n2o * 8) =
                make_float2(o[mh][n2o][2] * inv1, o[mh][n2o][3] * inv1);
        }
    }
}

extern "C" void kernel_launch(void* const* d_in, const int* in_sizes, int n_in,
                              void* d_out, int out_size)
{
    const float* q = (const float*)d_in[0];
    const float* k = (const float*)d_in[1];
    const float* v = (const float*)d_in[2];
    float* out = (float*)d_out;

    cudaFuncSetAttribute(attn_hmma2,
                         cudaFuncAttributeMaxDynamicSharedMemorySize, SMEM_BYTES);

    dim3 grid(32, 8, 2);   // qb, kv, batch
    attn_hmma2<<<grid, 256, SMEM_BYTES>>>(q, k, v, out);
}

// round 6
// speedup vs baseline: 1.2439x; 1.2439x over previous
#include <cuda_runtime.h>
#include <cuda_fp16.h>
#include <cstdint>

#define SS   2048
#define DQ   4096
#define DKV  1024
#define SCL  (0.08838834764831845f * 1.4426950408889634f)

// smem: K0 @0, K1 @16K, V0 @32K, V1 @48K, P @64K   (Q staged over K0+K1)
#define OFF_K0 0
#define OFF_V0 32768
#define OFF_P  65536
#define SMEM_BYTES 81920

__device__ __forceinline__ uint32_t smem_u32(const void* p) {
    uint32_t a;
    asm("{ .reg .u64 t; cvta.to.shared.u64 t, %1; cvt.u32.u64 %0, t; }" : "=r"(a) : "l"(p));
    return a;
}
__device__ __forceinline__ float fast_ex2(float x) {
    float y; asm("ex2.approx.ftz.f32 %0, %1;" : "=f"(y) : "f"(x)); return y;
}
__device__ __forceinline__ void ldsm_x4(uint32_t* r, uint32_t addr) {
    asm volatile("ldmatrix.sync.aligned.m8n8.x4.shared.b16 {%0,%1,%2,%3}, [%4];"
        : "=r"(r[0]), "=r"(r[1]), "=r"(r[2]), "=r"(r[3]) : "r"(addr));
}
__device__ __forceinline__ void ldsm_x4_t(uint32_t* r, uint32_t addr) {
    asm volatile("ldmatrix.sync.aligned.m8n8.x4.trans.shared.b16 {%0,%1,%2,%3}, [%4];"
        : "=r"(r[0]), "=r"(r[1]), "=r"(r[2]), "=r"(r[3]) : "r"(addr));
}
__device__ __forceinline__ void mma16816(float* d, const uint32_t* a, const uint32_t* b) {
    asm volatile("mma.sync.aligned.m16n8k16.row.col.f32.f16.f16.f32 "
        "{%0,%1,%2,%3},{%4,%5,%6,%7},{%8,%9},{%0,%1,%2,%3};"
        : "+f"(d[0]), "+f"(d[1]), "+f"(d[2]), "+f"(d[3])
        : "r"(a[0]), "r"(a[1]), "r"(a[2]), "r"(a[3]), "r"(b[0]), "r"(b[1]));
}
__device__ __forceinline__ uint32_t packh2(float a, float b) {
    __half2 h = __floats2half2_rn(a, b);
    return *(uint32_t*)&h;
}
__device__ __forceinline__ float h2sum(uint32_t u) {
    float2 f = __half22float2(*(__half2*)&u);
    return f.x + f.y;
}

// CTA: 4 heads x 32 tokens = 128 q-rows, 256 threads (8 warps), BN=64 keys/tile.
// QK: warp w -> rows (w>>1)*32 (M=32), keys (w&1)*32..+31.
// PV: warp w -> rows (w>>1)*32, hd cols (w&1)*64..+63.
__global__ void __launch_bounds__(256, 1)
attn_hmma3(const float* __restrict__ q, const float* __restrict__ k,
           const float* __restrict__ v, float* __restrict__ out)
{
    extern __shared__ char sm[];
    const uint32_t sb = smem_u32(sm);
    const uint32_t sP = sb + OFF_P;

    const int tid  = threadIdx.x;
    const int warp = tid >> 5, lane = tid & 31;
    const int qb = 63 - (int)blockIdx.x;      // longest CTAs first
    const int kv = blockIdx.y, b = blockIdx.z;
    const int q0 = qb * 32;
    const int hbase = kv * 4;
    const int ntiles = (qb >> 1) + 1;
    const int rg = warp >> 1;                 // row-group == head_local
    const int r0 = rg * 32;
    const int kh = (warp & 1) * 32;           // QK key-half
    const int ch = warp & 1;                  // PV col-half

    // ---- stage Q fp16 (pre-scaled) over K0+K1 region, 256B rows, swizzled ----
    #pragma unroll
    for (int it = 0; it < 8; ++it) {
        int id  = tid + 256 * it;
        int row = id >> 4, c16 = id & 15;
        int token = q0 + (row & 31);
        int head  = hbase + (row >> 5);
        const float4* gp = (const float4*)(q + (size_t)(b * SS + token) * DQ
                                             + head * 128 + c16 * 8);
        float4 f0 = gp[0], f1 = gp[1];
        uint32_t h0 = packh2(f0.x * SCL, f0.y * SCL);
        uint32_t h1 = packh2(f0.z * SCL, f0.w * SCL);
        uint32_t h2 = packh2(f1.x * SCL, f1.y * SCL);
        uint32_t h3 = packh2(f1.z * SCL, f1.w * SCL);
        uint32_t addr = sb + row * 256 + ((c16 ^ (row & 7)) << 4);
        asm volatile("st.shared.v4.b32 [%0],{%1,%2,%3,%4};"
            :: "r"(addr), "r"(h0), "r"(h1), "r"(h2), "r"(h3));
    }
    __syncthreads();

    // ---- persistent Q fragments, M=32: qf[kstep][mh][4] ----
    uint32_t qf[8][2][4];
    #pragma unroll
    for (int mh = 0; mh < 2; ++mh) {
        int row = r0 + mh * 16 + (lane & 7) + ((lane >> 3) & 1) * 8;
        #pragma unroll
        for (int ks = 0; ks < 8; ++ks) {
            int chunk = ks * 2 + (lane >> 4);
            ldsm_x4(qf[ks][mh], sb + row * 256 + ((chunk ^ (row & 7)) << 4));
        }
    }
    __syncthreads();   // Q region free for K/V buffers

    // ---- K/V gmem prefetch regs + smem store ----
    float4 kf[4][2], vf[4][2];
    auto ldkv = [&](int jt) {
        const float* kb_ = k + (size_t)(b * SS + jt * 64) * DKV + kv * 128;
        const float* vb_ = v + (size_t)(b * SS + jt * 64) * DKV + kv * 128;
        #pragma unroll
        for (int i = 0; i < 4; ++i) {
            int idx = tid + 256 * i;
            int row = idx >> 4, c16 = idx & 15;
            const float4* gk = (const float4*)(kb_ + (size_t)row * DKV + c16 * 8);
            const float4* gv = (const float4*)(vb_ + (size_t)row * DKV + c16 * 8);
            kf[i][0] = gk[0]; kf[i][1] = gk[1];
            vf[i][0] = gv[0]; vf[i][1] = gv[1];
        }
    };
    auto stkv = [&](int buf) {
        uint32_t dK = sb + OFF_K0 + buf * 16384;
        uint32_t dV = sb + OFF_V0 + buf * 16384;
        #pragma unroll
        for (int i = 0; i < 4; ++i) {
            int idx = tid + 256 * i;
            int row = idx >> 4, c16 = idx & 15;
            uint32_t off = row * 256 + ((c16 ^ (row & 7)) << 4);
            asm volatile("st.shared.v4.b32 [%0],{%1,%2,%3,%4};"
                :: "r"(dK + off),
                   "r"(packh2(kf[i][0].x, kf[i][0].y)), "r"(packh2(kf[i][0].z, kf[i][0].w)),
                   "r"(packh2(kf[i][1].x, kf[i][1].y)), "r"(packh2(kf[i][1].z, kf[i][1].w)));
            asm volatile("st.shared.v4.b32 [%0],{%1,%2,%3,%4};"
                :: "r"(dV + off),
                   "r"(packh2(vf[i][0].x, vf[i][0].y)), "r"(packh2(vf[i][0].z, vf[i][0].w)),
                   "r"(packh2(vf[i][1].x, vf[i][1].y)), "r"(packh2(vf[i][1].z, vf[i][1].w)));
        }
    };

    ldkv(0);
    stkv(0);
    __syncthreads();

    float o[2][8][4];
    #pragma unroll
    for (int mh = 0; mh < 2; ++mh)
        #pragma unroll
        for (int i = 0; i < 8; ++i)
            #pragma unroll
            for (int j = 0; j < 4; ++j) o[mh][i][j] = 0.0f;
    float lsum[2][2] = {{0.0f, 0.0f}, {0.0f, 0.0f}};

    const int m = lane >> 3;

    for (int jt = 0; jt < ntiles; ++jt) {
        const int cur = jt & 1;
        const uint32_t sK = sb + OFF_K0 + cur * 16384;
        const uint32_t sV = sb + OFF_V0 + cur * 16384;

        // ---- QK^T: M=32 x 32 keys (this warp's key-half) ----
        float s[4][2][4];
        #pragma unroll
        for (int n2 = 0; n2 < 4; ++n2)
            #pragma unroll
            for (int mh = 0; mh < 2; ++mh)
                #pragma unroll
                for (int j = 0; j < 4; ++j) s[n2][mh][j] = 0.0f;

        #pragma unroll
        for (int n2 = 0; n2 < 4; ++n2) {
            int kr = kh + n2 * 8 + (lane & 7);
            #pragma unroll
            for (int ks2 = 0; ks2 < 4; ++ks2) {
                uint32_t kb[4];
                int chunk = ks2 * 4 + m;
                ldsm_x4(kb, sK + kr * 256 + ((chunk ^ (kr & 7)) << 4));
                mma16816(s[n2][0], qf[2*ks2][0],   kb);
                mma16816(s[n2][0], qf[2*ks2+1][0], kb + 2);
                mma16816(s[n2][1], qf[2*ks2][1],   kb);
                mma16816(s[n2][1], qf[2*ks2+1][1], kb + 2);
            }
        }

        if (jt + 1 < ntiles) ldkv(jt + 1);   // overlaps softmax + PV

        // ---- softmax (no-rescale, base-2) + P -> smem ----
        #pragma unroll
        for (int n2 = 0; n2 < 4; ++n2) {
            int ng = (kh >> 3) + n2;   // global 8-key chunk in tile
            int kg = jt * 64 + kh + n2 * 8 + (lane & 3) * 2;
            #pragma unroll
            for (int mh = 0; mh < 2; ++mh) {
                int row0 = r0 + mh * 16 + (lane >> 2);
                int tok0 = q0 + mh * 16 + (lane >> 2);
                float p00 = (kg     <= tok0)     ? fast_ex2(s[n2][mh][0]) : 0.0f;
                float p01 = (kg + 1 <= tok0)     ? fast_ex2(s[n2][mh][1]) : 0.0f;
                float p10 = (kg     <= tok0 + 8) ? fast_ex2(s[n2][mh][2]) : 0.0f;
                float p11 = (kg + 1 <= tok0 + 8) ? fast_ex2(s[n2][mh][3]) : 0.0f;
                int r1 = row0 + 8;
                uint32_t a0 = sP + row0 * 128 + ((ng ^ (row0 & 7)) << 4) + (lane & 3) * 4;
                uint32_t a1 = sP + r1   * 128 + ((ng ^ (r1   & 7)) << 4) + (lane & 3) * 4;
                asm volatile("st.shared.b32 [%0], %1;" :: "r"(a0), "r"(packh2(p00, p01)));
                asm volatile("st.shared.b32 [%0], %1;" :: "r"(a1), "r"(packh2(p10, p11)));
            }
        }
        __syncthreads();   // P visible to partner warps

        // ---- PV: rows r0..r0+31 x cols ch*64..+63; l accumulated from pf ----
        #pragma unroll
        for (int ks2 = 0; ks2 < 4; ++ks2) {
            uint32_t pf[2][4];
            #pragma unroll
            for (int mh = 0; mh < 2; ++mh) {
                int row = r0 + mh * 16 + (lane & 7) + ((lane >> 3) & 1) * 8;
                int chunk = ks2 * 2 + (lane >> 4);
                ldsm_x4(pf[mh], sP + row * 128 + ((chunk ^ (row & 7)) << 4));
                lsum[mh][0] += h2sum(pf[mh][0]) + h2sum(pf[mh][2]);
                lsum[mh][1] += h2sum(pf[mh][1]) + h2sum(pf[mh][3]);
            }
            int Vrow = ks2 * 16 + (m & 1) * 8 + (lane & 7);
            #pragma unroll
            for (int p2 = 0; p2 < 4; ++p2) {
                uint32_t vb[4];
                int chunk = ch * 8 + p2 * 2 + (m >> 1);
                ldsm_x4_t(vb, sV + Vrow * 256 + ((chunk ^ (Vrow & 7)) << 4));
                mma16816(o[0][p2*2],     pf[0], vb);
                mma16816(o[0][p2*2 + 1], pf[0], vb + 2);
                mma16816(o[1][p2*2],     pf[1], vb);
                mma16816(o[1][p2*2 + 1], pf[1], vb + 2);
            }
        }

        if (jt + 1 < ntiles) stkv(cur ^ 1);   // write next tile into other buffer
        __syncthreads();
    }

    // ---- epilogue ----
    #pragma unroll
    for (int mh = 0; mh < 2; ++mh) {
        float l0 = lsum[mh][0], l1 = lsum[mh][1];
        l0 += __shfl_xor_sync(0xffffffffu, l0, 1);
        l0 += __shfl_xor_sync(0xffffffffu, l0, 2);
        l1 += __shfl_xor_sync(0xffffffffu, l1, 1);
        l1 += __shfl_xor_sync(0xffffffffu, l1, 2);
        float inv0 = 1.0f / l0, inv1 = 1.0f / l1;

        int tok0 = q0 + mh * 16 + (lane >> 2);
        int head = hbase + rg;
        float* r0p = out + (size_t)(b * SS + tok0) * DQ + head * 128
                   + ch * 64 + (lane & 3) * 2;
        float* r1p = r0p + (size_t)8 * DQ;
        #pragma unroll
        for (int p2 = 0; p2 < 8; ++p2) {
            *(float2*)(r0p + p2 * 8) =
                make_float2(o[mh][p2][0] * inv0, o[mh][p2][1] * inv0);
            *(float2*)(r1p + p2 * 8) =
                make_float2(o[mh][p2][2] * inv1, o[mh][p2][3] * inv1);
        }
    }
}

extern "C" void kernel_launch(void* const* d_in, const int* in_sizes, int n_in,
                              void* d_out, int out_size)
{
    const float* q = (const float*)d_in[0];
    const float* k = (const float*)d_in[1];
    const float* v = (const float*)d_in[2];
    float* out = (float*)d_out;

    cudaFuncSetAttribute(attn_hmma3,
                         cudaFuncAttributeMaxDynamicSharedMemorySize, SMEM_BYTES);

    dim3 grid(64, 8, 2);   // qb, kv, batch
    attn_hmma3<<<grid, 256, SMEM_BYTES>>>(q, k, v, out);
}

// round 7
// speedup vs baseline: 1.4042x; 1.1289x over previous
#include <cuda_runtime.h>
#include <cuda_fp16.h>
#include <cstdint>

#define SS   2048
#define DQ   4096
#define DKV  1024
#define SCL  (0.08838834764831845f * 1.4426950408889634f)

// smem: K0 @0, K1 @16K, V0 @32K, V1 @48K, P0 @64K, P1 @80K  (Q staged over K0+K1)
#define OFF_K0 0
#define OFF_V0 32768
#define OFF_P  65536
#define SMEM_BYTES 98304

__device__ __forceinline__ uint32_t smem_u32(const void* p) {
    uint32_t a;
    asm("{ .reg .u64 t; cvta.to.shared.u64 t, %1; cvt.u32.u64 %0, t; }" : "=r"(a) : "l"(p));
    return a;
}
__device__ __forceinline__ float fast_ex2(float x) {
    float y; asm("ex2.approx.ftz.f32 %0, %1;" : "=f"(y) : "f"(x)); return y;
}
__device__ __forceinline__ void ldsm_x4(uint32_t* r, uint32_t addr) {
    asm volatile("ldmatrix.sync.aligned.m8n8.x4.shared.b16 {%0,%1,%2,%3}, [%4];"
        : "=r"(r[0]), "=r"(r[1]), "=r"(r[2]), "=r"(r[3]) : "r"(addr));
}
__device__ __forceinline__ void ldsm_x4_t(uint32_t* r, uint32_t addr) {
    asm volatile("ldmatrix.sync.aligned.m8n8.x4.trans.shared.b16 {%0,%1,%2,%3}, [%4];"
        : "=r"(r[0]), "=r"(r[1]), "=r"(r[2]), "=r"(r[3]) : "r"(addr));
}
__device__ __forceinline__ void mma16816(float* d, const uint32_t* a, const uint32_t* b) {
    asm volatile("mma.sync.aligned.m16n8k16.row.col.f32.f16.f16.f32 "
        "{%0,%1,%2,%3},{%4,%5,%6,%7},{%8,%9},{%0,%1,%2,%3};"
        : "+f"(d[0]), "+f"(d[1]), "+f"(d[2]), "+f"(d[3])
        : "r"(a[0]), "r"(a[1]), "r"(a[2]), "r"(a[3]), "r"(b[0]), "r"(b[1]));
}
__device__ __forceinline__ uint32_t packh2(float a, float b) {
    __half2 h = __floats2half2_rn(a, b);
    return *(uint32_t*)&h;
}
__device__ __forceinline__ float h2sum(uint32_t u) {
    float2 f = __half22float2(*(__half2*)&u);
    return f.x + f.y;
}
__device__ __forceinline__ void bar_pair(int id) {
    asm volatile("bar.sync %0, 64;" :: "r"(id) : "memory");
}

// CTA: 4 heads x 32 tokens = 128 q-rows, 256 threads (8 warps), BN=64 keys/tile.
// QK: warp w -> rows (w>>1)*32 (M=32), keys (w&1)*32..+31.
// PV: warp w -> rows (w>>1)*32, hd cols (w&1)*64..+63.
__global__ void __launch_bounds__(256, 1)
attn_hmma4(const float* __restrict__ q, const float* __restrict__ k,
           const float* __restrict__ v, float* __restrict__ out)
{
    extern __shared__ char sm[];
    const uint32_t sb = smem_u32(sm);

    const int tid  = threadIdx.x;
    const int warp = tid >> 5, lane = tid & 31;
    const int qb = 63 - (int)blockIdx.x;      // longest CTAs first
    const int kv = blockIdx.y, b = blockIdx.z;
    const int q0 = qb * 32;
    const int hbase = kv * 4;
    const int ntiles = (qb >> 1) + 1;
    const int rg = warp >> 1;                 // row-group == head_local
    const int r0 = rg * 32;
    const int kh = (warp & 1) * 32;           // QK key-half
    const int ch = warp & 1;                  // PV col-half

    // ---- stage Q fp16 (pre-scaled) over K0+K1 region, 256B rows, swizzled ----
    #pragma unroll
    for (int it = 0; it < 8; ++it) {
        int id  = tid + 256 * it;
        int row = id >> 4, c16 = id & 15;
        int token = q0 + (row & 31);
        int head  = hbase + (row >> 5);
        const float4* gp = (const float4*)(q + (size_t)(b * SS + token) * DQ
                                             + head * 128 + c16 * 8);
        float4 f0 = gp[0], f1 = gp[1];
        uint32_t h0 = packh2(f0.x * SCL, f0.y * SCL);
        uint32_t h1 = packh2(f0.z * SCL, f0.w * SCL);
        uint32_t h2 = packh2(f1.x * SCL, f1.y * SCL);
        uint32_t h3 = packh2(f1.z * SCL, f1.w * SCL);
        uint32_t addr = sb + row * 256 + ((c16 ^ (row & 7)) << 4);
        asm volatile("st.shared.v4.b32 [%0],{%1,%2,%3,%4};"
            :: "r"(addr), "r"(h0), "r"(h1), "r"(h2), "r"(h3));
    }
    __syncthreads();

    // ---- persistent Q fragments, M=32: qf[kstep][mh][4] ----
    uint32_t qf[8][2][4];
    #pragma unroll
    for (int mh = 0; mh < 2; ++mh) {
        int row = r0 + mh * 16 + (lane & 7) + ((lane >> 3) & 1) * 8;
        #pragma unroll
        for (int ks = 0; ks < 8; ++ks) {
            int chunk = ks * 2 + (lane >> 4);
            ldsm_x4(qf[ks][mh], sb + row * 256 + ((chunk ^ (row & 7)) << 4));
        }
    }
    __syncthreads();   // Q region free for K/V buffers

    // ---- K/V gmem prefetch regs + smem store ----
    float4 kf[4][2], vf[4][2];
    auto ldkv = [&](int jt) {
        const float* kb_ = k + (size_t)(b * SS + jt * 64) * DKV + kv * 128;
        const float* vb_ = v + (size_t)(b * SS + jt * 64) * DKV + kv * 128;
        #pragma unroll
        for (int i = 0; i < 4; ++i) {
            int idx = tid + 256 * i;
            int row = idx >> 4, c16 = idx & 15;
            const float4* gk = (const float4*)(kb_ + (size_t)row * DKV + c16 * 8);
            const float4* gv = (const float4*)(vb_ + (size_t)row * DKV + c16 * 8);
            kf[i][0] = gk[0]; kf[i][1] = gk[1];
            vf[i][0] = gv[0]; vf[i][1] = gv[1];
        }
    };
    auto stkv = [&](int buf) {
        uint32_t dK = sb + OFF_K0 + buf * 16384;
        uint32_t dV = sb + OFF_V0 + buf * 16384;
        #pragma unroll
        for (int i = 0; i < 4; ++i) {
            int idx = tid + 256 * i;
            int row = idx >> 4, c16 = idx & 15;
            uint32_t off = row * 256 + ((c16 ^ (row & 7)) << 4);
            asm volatile("st.shared.v4.b32 [%0],{%1,%2,%3,%4};"
                :: "r"(dK + off),
                   "r"(packh2(kf[i][0].x, kf[i][0].y)), "r"(packh2(kf[i][0].z, kf[i][0].w)),
                   "r"(packh2(kf[i][1].x, kf[i][1].y)), "r"(packh2(kf[i][1].z, kf[i][1].w)));
            asm volatile("st.shared.v4.b32 [%0],{%1,%2,%3,%4};"
                :: "r"(dV + off),
                   "r"(packh2(vf[i][0].x, vf[i][0].y)), "r"(packh2(vf[i][0].z, vf[i][0].w)),
                   "r"(packh2(vf[i][1].x, vf[i][1].y)), "r"(packh2(vf[i][1].z, vf[i][1].w)));
        }
    };

    ldkv(0);
    stkv(0);
    __syncthreads();

    float o[2][8][4];
    #pragma unroll
    for (int mh = 0; mh < 2; ++mh)
        #pragma unroll
        for (int i = 0; i < 8; ++i)
            #pragma unroll
            for (int j = 0; j < 4; ++j) o[mh][i][j] = 0.0f;
    float lsum[2][2] = {{0.0f, 0.0f}, {0.0f, 0.0f}};

    const int m = lane >> 3;

    for (int jt = 0; jt < ntiles; ++jt) {
        const int cur = jt & 1;
        const uint32_t sK = sb + OFF_K0 + cur * 16384;
        const uint32_t sV = sb + OFF_V0 + cur * 16384;
        const uint32_t sP = sb + OFF_P  + cur * 16384;

        // ---- QK^T: M=32 x 32 keys (this warp's key-half) ----
        float s[4][2][4];
        #pragma unroll
        for (int n2 = 0; n2 < 4; ++n2)
            #pragma unroll
            for (int mh = 0; mh < 2; ++mh)
                #pragma unroll
                for (int j = 0; j < 4; ++j) s[n2][mh][j] = 0.0f;

        #pragma unroll
        for (int n2 = 0; n2 < 4; ++n2) {
            int kr = kh + n2 * 8 + (lane & 7);
            #pragma unroll
            for (int ks2 = 0; ks2 < 4; ++ks2) {
                uint32_t kb[4];
                int chunk = ks2 * 4 + m;
                ldsm_x4(kb, sK + kr * 256 + ((chunk ^ (kr & 7)) << 4));
                mma16816(s[n2][0], qf[2*ks2][0],   kb);
                mma16816(s[n2][0], qf[2*ks2+1][0], kb + 2);
                mma16816(s[n2][1], qf[2*ks2][1],   kb);
                mma16816(s[n2][1], qf[2*ks2+1][1], kb + 2);
            }
        }

        // ---- softmax (no-rescale, base-2) + P -> smem (s dies here) ----
        #pragma unroll
        for (int n2 = 0; n2 < 4; ++n2) {
            int ng = (kh >> 3) + n2;   // global 8-key chunk in tile
            int kg = jt * 64 + kh + n2 * 8 + (lane & 3) * 2;
            #pragma unroll
            for (int mh = 0; mh < 2; ++mh) {
                int row0 = r0 + mh * 16 + (lane >> 2);
                int tok0 = q0 + mh * 16 + (lane >> 2);
                float p00 = (kg     <= tok0)     ? fast_ex2(s[n2][mh][0]) : 0.0f;
                float p01 = (kg + 1 <= tok0)     ? fast_ex2(s[n2][mh][1]) : 0.0f;
                float p10 = (kg     <= tok0 + 8) ? fast_ex2(s[n2][mh][2]) : 0.0f;
                float p11 = (kg + 1 <= tok0 + 8) ? fast_ex2(s[n2][mh][3]) : 0.0f;
                int r1 = row0 + 8;
                uint32_t a0 = sP + row0 * 128 + ((ng ^ (row0 & 7)) << 4) + (lane & 3) * 4;
                uint32_t a1 = sP + r1   * 128 + ((ng ^ (r1   & 7)) << 4) + (lane & 3) * 4;
                asm volatile("st.shared.b32 [%0], %1;" :: "r"(a0), "r"(packh2(p00, p01)));
                asm volatile("st.shared.b32 [%0], %1;" :: "r"(a1), "r"(packh2(p10, p11)));
            }
        }

        // ---- issue next-tile LDG now (s regs dead -> no spill pressure) ----
        if (jt + 1 < ntiles) ldkv(jt + 1);

        bar_pair(rg + 1);   // partner warp's P half visible (64-thread barrier)

        // ---- PV: rows r0..r0+31 x cols ch*64..+63; l accumulated from pf ----
        #pragma unroll
        for (int ks2 = 0; ks2 < 4; ++ks2) {
            uint32_t pf[2][4];
            #pragma unroll
            for (int mh = 0; mh < 2; ++mh) {
                int row = r0 + mh * 16 + (lane & 7) + ((lane >> 3) & 1) * 8;
                int chunk = ks2 * 2 + (lane >> 4);
                ldsm_x4(pf[mh], sP + row * 128 + ((chunk ^ (row & 7)) << 4));
                lsum[mh][0] += h2sum(pf[mh][0]) + h2sum(pf[mh][2]);
                lsum[mh][1] += h2sum(pf[mh][1]) + h2sum(pf[mh][3]);
            }
            int Vrow = ks2 * 16 + (m & 1) * 8 + (lane & 7);
            #pragma unroll
            for (int p2 = 0; p2 < 4; ++p2) {
                uint32_t vb[4];
                int chunk = ch * 8 + p2 * 2 + (m >> 1);
                ldsm_x4_t(vb, sV + Vrow * 256 + ((chunk ^ (Vrow & 7)) << 4));
                mma16816(o[0][p2*2],     pf[0], vb);
                mma16816(o[0][p2*2 + 1], pf[0], vb + 2);
                mma16816(o[1][p2*2],     pf[1], vb);
                mma16816(o[1][p2*2 + 1], pf[1], vb + 2);
            }
        }

        if (jt + 1 < ntiles) stkv(cur ^ 1);   // write next tile into other buffer
        __syncthreads();                       // K/V swap barrier (only full sync)
    }

    // ---- epilogue ----
    #pragma unroll
    for (int mh = 0; mh < 2; ++mh) {
        float l0 = lsum[mh][0], l1 = lsum[mh][1];
        l0 += __shfl_xor_sync(0xffffffffu, l0, 1);
        l0 += __shfl_xor_sync(0xffffffffu, l0, 2);
        l1 += __shfl_xor_sync(0xffffffffu, l1, 1);
        l1 += __shfl_xor_sync(0xffffffffu, l1, 2);
        float inv0 = 1.0f / l0, inv1 = 1.0f / l1;

        int tok0 = q0 + mh * 16 + (lane >> 2);
        int head = hbase + rg;
        float* r0p = out + (size_t)(b * SS + tok0) * DQ + head * 128
                   + ch * 64 + (lane & 3) * 2;
        float* r1p = r0p + (size_t)8 * DQ;
        #pragma unroll
        for (int p2 = 0; p2 < 8; ++p2) {
            *(float2*)(r0p + p2 * 8) =
                make_float2(o[mh][p2][0] * inv0, o[mh][p2][1] * inv0);
            *(float2*)(r1p + p2 * 8) =
                make_float2(o[mh][p2][2] * inv1, o[mh][p2][3] * inv1);
        }
    }
}

extern "C" void kernel_launch(void* const* d_in, const int* in_sizes, int n_in,
                              void* d_out, int out_size)
{
    const float* q = (const float*)d_in[0];
    const float* k = (const float*)d_in[1];
    const float* v = (const float*)d_in[2];
    float* out = (float*)d_out;

    cudaFuncSetAttribute(attn_hmma4,
                         cudaFuncAttributeMaxDynamicSharedMemorySize, SMEM_BYTES);

    dim3 grid(64, 8, 2);   // qb, kv, batch
    attn_hmma4<<<grid, 256, SMEM_BYTES>>>(q, k, v, out);
}